// round 10
// baseline (speedup 1.0000x reference)
#include <cuda_runtime.h>

// Sum-reduce 20M fp32 values (full sparse sum == values.sum(); indices unused).
// HBM-bound streaming read of 80 MB. Single fused kernel (last-block-counter
// finalize — R6 win). R9/R10 experiment: isolate the R5 confound by adding ONLY
// a 2-way strided unroll with independent accumulators (NO __ldcs). Tests
// whether the R5 regression was the cache hint (expected) or the manual unroll.
// R10 = R9 resubmitted after infra failure.

__device__ float         g_partial = 0.0f;
__device__ unsigned int  g_count   = 0;

__global__ void __launch_bounds__(256) sum_kernel(const float* __restrict__ vals,
                                                  long long n, float* __restrict__ out,
                                                  int nblocks) {
    long long n4 = n >> 2;  // number of float4s
    const float4* v4 = reinterpret_cast<const float4*>(vals);

    long long idx    = blockIdx.x * (long long)blockDim.x + threadIdx.x;
    long long stride = (long long)gridDim.x * blockDim.x;

    float a0 = 0.0f, a1 = 0.0f;

    long long i = idx;
    for (; i + stride < n4; i += 2 * stride) {
        float4 v0 = v4[i];
        float4 v1 = v4[i + stride];
        a0 += (v0.x + v0.y) + (v0.z + v0.w);
        a1 += (v1.x + v1.y) + (v1.z + v1.w);
    }
    for (; i < n4; i += stride) {
        float4 v = v4[i];
        a0 += (v.x + v.y) + (v.z + v.w);
    }
    // scalar tail (n not divisible by 4)
    for (long long j = (n4 << 2) + idx; j < n; j += stride) {
        a0 += vals[j];
    }

    float acc = a0 + a1;

    // warp reduce
    #pragma unroll
    for (int off = 16; off > 0; off >>= 1)
        acc += __shfl_down_sync(0xFFFFFFFFu, acc, off);

    __shared__ float warp_sums[8];  // 256 threads = 8 warps
    int lane = threadIdx.x & 31;
    int wid  = threadIdx.x >> 5;
    if (lane == 0) warp_sums[wid] = acc;
    __syncthreads();

    if (wid == 0) {
        float s = (lane < 8) ? warp_sums[lane] : 0.0f;
        #pragma unroll
        for (int off = 4; off > 0; off >>= 1)
            s += __shfl_down_sync(0xFFFFFFFFu, s, off);

        if (lane == 0) {
            atomicAdd(&g_partial, s);
            __threadfence();
            unsigned int done = atomicAdd(&g_count, 1u);
            if (done == (unsigned int)nblocks - 1u) {
                // last block: publish result and reset scratch for next replay
                out[0]    = g_partial;
                g_partial = 0.0f;
                g_count   = 0u;
            }
        }
    }
}

extern "C" void kernel_launch(void* const* d_in, const int* in_sizes, int n_in,
                              void* d_out, int out_size) {
    const float* vals = (const float*)d_in[0];
    long long n = (long long)in_sizes[0];
    float* out = (float*)d_out;

    int grid = 148 * 8;  // 1184 blocks = exactly one full-occupancy wave
    sum_kernel<<<grid, 256>>>(vals, n, out, grid);
}

// round 11
// speedup vs baseline: 1.0303x; 1.0303x over previous
#include <cuda_runtime.h>

// Sum-reduce 20M fp32 values (full sparse sum == values.sum(); indices unused).
// HBM-bound streaming read of 80 MB. Single fused kernel (last-block-counter
// finalize). R11: keep the 2-way strided unroll with independent accumulators
// (best DRAM%: 59.2% / 4687 GB/s profiled; R5's regression was the __ldcs hint,
// now confirmed). Geometry: 512-thread blocks x 592 grid — same 303K threads,
// half the blocks -> half the finalize atomics and block tails.

__device__ float         g_partial = 0.0f;
__device__ unsigned int  g_count   = 0;

__global__ void __launch_bounds__(512) sum_kernel(const float* __restrict__ vals,
                                                  long long n, float* __restrict__ out,
                                                  int nblocks) {
    long long n4 = n >> 2;  // number of float4s
    const float4* v4 = reinterpret_cast<const float4*>(vals);

    long long idx    = blockIdx.x * (long long)blockDim.x + threadIdx.x;
    long long stride = (long long)gridDim.x * blockDim.x;

    float a0 = 0.0f, a1 = 0.0f;

    long long i = idx;
    for (; i + stride < n4; i += 2 * stride) {
        float4 v0 = v4[i];
        float4 v1 = v4[i + stride];
        a0 += (v0.x + v0.y) + (v0.z + v0.w);
        a1 += (v1.x + v1.y) + (v1.z + v1.w);
    }
    for (; i < n4; i += stride) {
        float4 v = v4[i];
        a0 += (v.x + v.y) + (v.z + v.w);
    }
    // scalar tail (n not divisible by 4)
    for (long long j = (n4 << 2) + idx; j < n; j += stride) {
        a0 += vals[j];
    }

    float acc = a0 + a1;

    // warp reduce
    #pragma unroll
    for (int off = 16; off > 0; off >>= 1)
        acc += __shfl_down_sync(0xFFFFFFFFu, acc, off);

    __shared__ float warp_sums[16];  // 512 threads = 16 warps
    int lane = threadIdx.x & 31;
    int wid  = threadIdx.x >> 5;
    if (lane == 0) warp_sums[wid] = acc;
    __syncthreads();

    if (wid == 0) {
        float s = (lane < 16) ? warp_sums[lane] : 0.0f;
        #pragma unroll
        for (int off = 8; off > 0; off >>= 1)
            s += __shfl_down_sync(0xFFFFFFFFu, s, off);

        if (lane == 0) {
            atomicAdd(&g_partial, s);
            __threadfence();
            unsigned int done = atomicAdd(&g_count, 1u);
            if (done == (unsigned int)nblocks - 1u) {
                // last block: publish result and reset scratch for next replay
                out[0]    = g_partial;
                g_partial = 0.0f;
                g_count   = 0u;
            }
        }
    }
}

extern "C" void kernel_launch(void* const* d_in, const int* in_sizes, int n_in,
                              void* d_out, int out_size) {
    const float* vals = (const float*)d_in[0];
    long long n = (long long)in_sizes[0];
    float* out = (float*)d_out;

    int grid = 148 * 4;  // 592 blocks x 512 threads = one full-occupancy wave
    sum_kernel<<<grid, 512>>>(vals, n, out, grid);
}

// round 12
// speedup vs baseline: 1.1148x; 1.0820x over previous
#include <cuda_runtime.h>

// Sum-reduce 20M fp32 values (full sparse sum == values.sum(); indices unused).
// HBM-bound streaming read of 80 MB. Single fused kernel (last-block-counter
// finalize). R12: 4-way strided unroll, independent accumulators (no __ldcs —
// confirmed harmful in R5/R10), 32-bit hot-loop indexing. 512 threads x 592
// blocks = one full-occupancy wave.

__device__ float         g_partial = 0.0f;
__device__ unsigned int  g_count   = 0;

__global__ void __launch_bounds__(512) sum_kernel(const float* __restrict__ vals,
                                                  long long n, float* __restrict__ out,
                                                  int nblocks) {
    unsigned int n4 = (unsigned int)(n >> 2);  // number of float4s (5M, fits u32)
    const float4* v4 = reinterpret_cast<const float4*>(vals);

    unsigned int idx    = blockIdx.x * blockDim.x + threadIdx.x;
    unsigned int stride = gridDim.x * blockDim.x;

    float a0 = 0.0f, a1 = 0.0f, a2 = 0.0f, a3 = 0.0f;

    unsigned int i = idx;
    for (; i + 3u * stride < n4; i += 4u * stride) {
        float4 v0 = v4[i];
        float4 v1 = v4[i + stride];
        float4 v2 = v4[i + 2u * stride];
        float4 v3 = v4[i + 3u * stride];
        a0 += (v0.x + v0.y) + (v0.z + v0.w);
        a1 += (v1.x + v1.y) + (v1.z + v1.w);
        a2 += (v2.x + v2.y) + (v2.z + v2.w);
        a3 += (v3.x + v3.y) + (v3.z + v3.w);
    }
    for (; i < n4; i += stride) {
        float4 v = v4[i];
        a0 += (v.x + v.y) + (v.z + v.w);
    }
    // scalar tail (n not divisible by 4)
    for (long long j = ((long long)n4 << 2) + idx; j < n; j += stride) {
        a0 += vals[j];
    }

    float acc = (a0 + a1) + (a2 + a3);

    // warp reduce
    #pragma unroll
    for (int off = 16; off > 0; off >>= 1)
        acc += __shfl_down_sync(0xFFFFFFFFu, acc, off);

    __shared__ float warp_sums[16];  // 512 threads = 16 warps
    int lane = threadIdx.x & 31;
    int wid  = threadIdx.x >> 5;
    if (lane == 0) warp_sums[wid] = acc;
    __syncthreads();

    if (wid == 0) {
        float s = (lane < 16) ? warp_sums[lane] : 0.0f;
        #pragma unroll
        for (int off = 8; off > 0; off >>= 1)
            s += __shfl_down_sync(0xFFFFFFFFu, s, off);

        if (lane == 0) {
            atomicAdd(&g_partial, s);
            __threadfence();
            unsigned int done = atomicAdd(&g_count, 1u);
            if (done == (unsigned int)nblocks - 1u) {
                // last block: publish result and reset scratch for next replay
                out[0]    = g_partial;
                g_partial = 0.0f;
                g_count   = 0u;
            }
        }
    }
}

extern "C" void kernel_launch(void* const* d_in, const int* in_sizes, int n_in,
                              void* d_out, int out_size) {
    const float* vals = (const float*)d_in[0];
    long long n = (long long)in_sizes[0];
    float* out = (float*)d_out;

    int grid = 148 * 4;  // 592 blocks x 512 threads = one full-occupancy wave
    sum_kernel<<<grid, 512>>>(vals, n, out, grid);
}